// round 2
// baseline (speedup 1.0000x reference)
#include <cuda_runtime.h>
#include <math.h>

#define C_DIM 384
#define G_DIM 383
#define M_DIM 384
#define EPS_F 1e-5f
#define NPAIR 73536   // M*(M-1)/2 = 384*383/2

// Scratch (no allocation allowed in kernel_launch)
__device__ float g_sum[G_DIM];
__device__ float g_sumsq[G_DIM];
__device__ int   g_cnt[G_DIM];
__device__ float g_proto[M_DIM];
__device__ float g_std[M_DIM];
__device__ float g_U[M_DIM * M_DIM];   // U[a*384 + x] = |p_x - p_a| / (sqrtC*|..| + eps)
__device__ int   g_pairs[NPAIR];       // a | (b << 16), b > a

__device__ __forceinline__ float rcpa(float x) {
    float r;
    asm("rcp.approx.f32 %0, %1;" : "=f"(r) : "f"(x));
    return r;
}

// ---------------- Kernel 0: zero accumulators + output ----------------
__global__ void k_zero(float* out) {
    int t = blockIdx.x * blockDim.x + threadIdx.x;
    if (t < G_DIM) { g_sum[t] = 0.f; g_sumsq[t] = 0.f; g_cnt[t] = 0; }
    if (t == 0) out[0] = 0.f;
}

// ---------------- Kernel 1: per-group count/sum/sumsq (one warp per 2 rows) ----
__global__ void k_accum(const float4* __restrict__ pred,
                        const int* __restrict__ tgt, int nrows) {
    int w    = (blockIdx.x * blockDim.x + threadIdx.x) >> 5;
    int lane = threadIdx.x & 31;
    int r0 = w * 2;
    if (r0 >= nrows) return;
    bool two = (r0 + 1) < nrows;

    const float4* rowA = pred + (size_t)r0 * (C_DIM / 4);
    const float4* rowB = rowA + (C_DIM / 4);

    float4 va[3], vb[3];
#pragma unroll
    for (int i = 0; i < 3; i++) va[i] = __ldcs(&rowA[lane + 32 * i]);
    if (two) {
#pragma unroll
        for (int i = 0; i < 3; i++) vb[i] = __ldcs(&rowB[lane + 32 * i]);
    } else {
#pragma unroll
        for (int i = 0; i < 3; i++) vb[i] = make_float4(0.f, 0.f, 0.f, 0.f);
    }

    float sA = 0.f, ssA = 0.f, sB = 0.f, ssB = 0.f;
#pragma unroll
    for (int i = 0; i < 3; i++) {
        sA += (va[i].x + va[i].y) + (va[i].z + va[i].w);
        ssA = fmaf(va[i].x, va[i].x, ssA);
        ssA = fmaf(va[i].y, va[i].y, ssA);
        ssA = fmaf(va[i].z, va[i].z, ssA);
        ssA = fmaf(va[i].w, va[i].w, ssA);
        sB += (vb[i].x + vb[i].y) + (vb[i].z + vb[i].w);
        ssB = fmaf(vb[i].x, vb[i].x, ssB);
        ssB = fmaf(vb[i].y, vb[i].y, ssB);
        ssB = fmaf(vb[i].z, vb[i].z, ssB);
        ssB = fmaf(vb[i].w, vb[i].w, ssB);
    }
#pragma unroll
    for (int o = 16; o; o >>= 1) {
        sA  += __shfl_down_sync(0xffffffffu, sA,  o);
        ssA += __shfl_down_sync(0xffffffffu, ssA, o);
        sB  += __shfl_down_sync(0xffffffffu, sB,  o);
        ssB += __shfl_down_sync(0xffffffffu, ssB, o);
    }
    if (lane == 0) {
        int gA = tgt[r0];
        atomicAdd(&g_sum[gA],   sA);
        atomicAdd(&g_sumsq[gA], ssA);
        atomicAdd(&g_cnt[gA],   1);
        if (two) {
            int gB = tgt[r0 + 1];
            atomicAdd(&g_sum[gB],   sB);
            atomicAdd(&g_sumsq[gB], ssB);
            atomicAdd(&g_cnt[gB],   1);
        }
    }
}

// ---------------- Kernel 2: mean / std per group ----------------
__global__ void k_stats() {
    int g = threadIdx.x;
    if (g >= M_DIM) return;
    float mean = 0.f, sd = 0.f;
    if (g < G_DIM) {
        float n = (float)g_cnt[g];
        if (n > 0.f) {
            float cnt = n * (float)C_DIM;
            float sum = g_sum[g];
            mean = sum / cnt;
            float ssq = g_sumsq[g] - sum * mean;   // sumsq - sum^2/cnt
            if (ssq < 0.f) ssq = 0.f;
            sd = (n > 1.f) ? sqrtf(ssq / fmaxf(cnt - 1.f, 1.f)) : 0.f;
        }
    }
    g_proto[g] = mean;   // slot 383 stays 0 (padded object slot)
    g_std[g]   = sd;
}

// ---------------- Kernel 3: build U table + triu pair list ----------------
// block = a (384), thread = x (384)
__global__ void k_u_pairs() {
    int a = blockIdx.x;
    int x = threadIdx.x;
    const float SQC = 19.595917942265423f;  // sqrt(384)
    float pa = g_proto[a];
    float d  = fabsf(g_proto[x] - pa);
    g_U[a * M_DIM + x] = d * rcpa(fmaf(SQC, d, EPS_F));   // 0 when x == a
    if (x > a) {
        int base = a * (M_DIM - 1) - (a * (a - 1)) / 2;   // pairs with first idx < a
        g_pairs[base + x - a - 1] = a | (x << 16);
    }
}

// ---------------- Kernel 4: masked mean over M^3, thread = (a,b) pair ------
// V[x,a,b] = w / (norm_ab + w + eps), w = (std_a+std_b)*U[a][x].
// Uniform 384-trip inner loop over x; 2 divisions fused per rcp.
__global__ void k_reduce(float* __restrict__ out) {
    __shared__ float red[8];
    int tid = threadIdx.x;
    int gid = blockIdx.x * blockDim.x + tid;

    const float SQC = 19.595917942265423f;
    float acc = 0.f;

    if (gid < NPAIR) {
        int p = g_pairs[gid];
        int a = p & 0xffff;
        int b = p >> 16;
        float sab = g_std[a] + g_std[b];
        float nrm = fmaf(SQC, fabsf(g_proto[b] - g_proto[a]), EPS_F);
        const float4* U = (const float4*)(g_U + a * M_DIM);

        float acc0 = 0.f, acc1 = 0.f;
#pragma unroll 8
        for (int i = 0; i < M_DIM / 4; i++) {
            float4 u = __ldg(&U[i]);          // broadcast within warp (a const)
            float w0 = sab * u.x;
            float w1 = sab * u.y;
            float w2 = sab * u.z;
            float w3 = sab * u.w;
            float d0 = nrm + w0;
            float d1 = nrm + w1;
            float d2 = nrm + w2;
            float d3 = nrm + w3;
            float r01 = rcpa(d0 * d1);
            float r23 = rcpa(d2 * d3);
            acc0 = fmaf(w0 * d1, r01, acc0);
            acc1 = fmaf(w1 * d0, r01, acc1);
            acc0 = fmaf(w2 * d3, r23, acc0);
            acc1 = fmaf(w3 * d2, r23, acc1);
        }
        acc = acc0 + acc1;
    }

    // block reduction
#pragma unroll
    for (int o = 16; o; o >>= 1) acc += __shfl_down_sync(0xffffffffu, acc, o);
    if ((tid & 31) == 0) red[tid >> 5] = acc;
    __syncthreads();
    if (tid < 8) {
        float v = red[tid];
#pragma unroll
        for (int o = 4; o; o >>= 1) v += __shfl_down_sync(0x000000ffu, v, o);
        if (tid == 0) {
            const float inv_m3 = 1.0f / ((float)M_DIM * (float)M_DIM * (float)M_DIM);
            atomicAdd(out, v * inv_m3);
        }
    }
}

extern "C" void kernel_launch(void* const* d_in, const int* in_sizes, int n_in,
                              void* d_out, int out_size) {
    const float* pred = (const float*)d_in[0];
    const int*   tgt  = (const int*)d_in[1];
    float*       out  = (float*)d_out;
    int nrows = in_sizes[1];                // 200000

    k_zero<<<2, 256>>>(out);

    int warps  = (nrows + 1) / 2;           // 2 rows per warp
    int blocks = (warps * 32 + 255) / 256;
    k_accum<<<blocks, 256>>>((const float4*)pred, tgt, nrows);

    k_stats<<<1, M_DIM>>>();
    k_u_pairs<<<M_DIM, M_DIM>>>();
    k_reduce<<<(NPAIR + 255) / 256, 256>>>(out);
}